// round 1
// baseline (speedup 1.0000x reference)
#include <cuda_runtime.h>
#include <math.h>

#define GRIDSZ   1024
#define NAGENTS  262144
#define NCH      8
#define NHID     64
#define DT       0.1f
#define SENS_ANG 0.6f
#define SENS_LEN 3.0f
#define DECAY    0.99f

// Scratch (static __device__ arrays: allocation-free per harness rules)
__device__ float g_latT[GRIDSZ * GRIDSZ * NCH];    // lattice transposed to (x,y,c), 32 MB
__device__ float g_dpher[NAGENTS * NCH];           // per-agent d_pheromone, 8 MB
__device__ int   g_winner[GRIDSZ * GRIDSZ];        // 0 = none, else agent_id+1 (zero-init, reset by latout)

// ---------------------------------------------------------------------------
// Kernel 1: transpose lattice (C,G,G) -> (G,G,C) so one cell's channels are a
// single 32B sector and a 3-cell row segment is 96 contiguous bytes.
// ---------------------------------------------------------------------------
__global__ void __launch_bounds__(256) transpose_k(const float* __restrict__ lat) {
    int idx = blockIdx.x * blockDim.x + threadIdx.x;   // x*GRIDSZ + y
    if (idx >= GRIDSZ * GRIDSZ) return;
    float4 a, b;
    a.x = lat[0 * GRIDSZ * GRIDSZ + idx];
    a.y = lat[1 * GRIDSZ * GRIDSZ + idx];
    a.z = lat[2 * GRIDSZ * GRIDSZ + idx];
    a.w = lat[3 * GRIDSZ * GRIDSZ + idx];
    b.x = lat[4 * GRIDSZ * GRIDSZ + idx];
    b.y = lat[5 * GRIDSZ * GRIDSZ + idx];
    b.z = lat[6 * GRIDSZ * GRIDSZ + idx];
    b.w = lat[7 * GRIDSZ * GRIDSZ + idx];
    float4* dst = reinterpret_cast<float4*>(&g_latT[(size_t)idx * NCH]);
    dst[0] = a;
    dst[1] = b;
}

// fast tanh: 1 - 2/(exp(2a)+1); exact saturation at +-inf, ~1e-7 rel error
__device__ __forceinline__ float fast_tanh(float a) {
    float t = __expf(2.0f * a);
    return 1.0f - __fdividef(2.0f, t + 1.0f);
}

// ---------------------------------------------------------------------------
// Kernel 2: per-agent sense + MLP + outputs + scatter bookkeeping
// ---------------------------------------------------------------------------
__global__ void __launch_bounds__(256) agent_k(
    const float* __restrict__ pos, const float* __restrict__ vel,
    const float* __restrict__ W1, const float* __restrict__ b1,
    const float* __restrict__ W2, const float* __restrict__ b2,
    float* __restrict__ out)
{
    // Shared weights: W1 transposed to [j][i] (row=hidden, 24 floats, 96B -> f4 aligned),
    // W2 padded to [j][12] so rows are float4-loadable.
    __shared__ float sW1t[NHID * 24];
    __shared__ float sW2p[NHID * 12];
    __shared__ float sb1[NHID];
    __shared__ float sb2[12];

    int tid = threadIdx.x;
    for (int t = tid; t < 24 * NHID; t += blockDim.x) {
        int ii = t / NHID, j = t % NHID;
        sW1t[j * 24 + ii] = W1[t];
    }
    for (int t = tid; t < NHID * 12; t += blockDim.x) {
        int j = t / 12, k = t % 12;
        sW2p[t] = (k < 10) ? W2[j * 10 + k] : 0.0f;
    }
    if (tid < NHID) sb1[tid] = b1[tid];
    if (tid < 12)   sb2[tid] = (tid < 10) ? b2[tid] : 0.0f;
    __syncthreads();

    int i = blockIdx.x * blockDim.x + tid;
    if (i >= NAGENTS) return;

    float px = pos[i], py = pos[NAGENTS + i];
    float vx = vel[i], vy = vel[NAGENTS + i];

    float theta = atan2f(vy, vx);
    const float offs[3] = {0.0f, SENS_ANG, -SENS_ANG};

    float feat[24];
    #pragma unroll
    for (int s = 0; s < 3; s++) {
        float sn, cs;
        sincosf(theta + offs[s], &sn, &cs);
        // match JAX mul-then-add rounding (no fma contraction before rint)
        int cx = (int)rintf(__fadd_rn(px, __fmul_rn(SENS_LEN, cs)));
        int cy = (int)rintf(__fadd_rn(py, __fmul_rn(SENS_LEN, sn)));

        float acc[NCH];
        #pragma unroll
        for (int c = 0; c < NCH; c++) acc[c] = 0.0f;

        bool fast = (cy >= 1) && (cy <= GRIDSZ - 2);
        #pragma unroll
        for (int dx = -1; dx <= 1; dx++) {
            int x = (cx + dx + 2 * GRIDSZ) & (GRIDSZ - 1);
            if (fast) {
                const float4* p = reinterpret_cast<const float4*>(
                    &g_latT[((size_t)x * GRIDSZ + (cy - 1)) * NCH]);
                #pragma unroll
                for (int q = 0; q < 6; q++) {
                    float4 v = p[q];
                    int bse = (q & 1) * 4;
                    acc[bse + 0] += v.x; acc[bse + 1] += v.y;
                    acc[bse + 2] += v.z; acc[bse + 3] += v.w;
                }
            } else {
                #pragma unroll
                for (int dy = -1; dy <= 1; dy++) {
                    int y = (cy + dy + 2 * GRIDSZ) & (GRIDSZ - 1);
                    const float4* p = reinterpret_cast<const float4*>(
                        &g_latT[((size_t)x * GRIDSZ + y) * NCH]);
                    float4 v0 = p[0], v1 = p[1];
                    acc[0] += v0.x; acc[1] += v0.y; acc[2] += v0.z; acc[3] += v0.w;
                    acc[4] += v1.x; acc[5] += v1.y; acc[6] += v1.z; acc[7] += v1.w;
                }
            }
        }
        #pragma unroll
        for (int c = 0; c < NCH; c++) feat[s * NCH + c] = acc[c];
    }

    // MLP: o[k] = b2[k] + sum_j tanh(b1[j] + sum_i feat[i] W1[i][j]) * W2[j][k]
    float o[12];
    #pragma unroll
    for (int k = 0; k < 12; k++) o[k] = sb2[k];

    for (int j = 0; j < NHID; j++) {
        float a = sb1[j];
        const float4* w1r = reinterpret_cast<const float4*>(&sW1t[j * 24]);
        #pragma unroll
        for (int q = 0; q < 6; q++) {
            float4 w = w1r[q];
            a += feat[q * 4 + 0] * w.x + feat[q * 4 + 1] * w.y
               + feat[q * 4 + 2] * w.z + feat[q * 4 + 3] * w.w;
        }
        float h = fast_tanh(a);
        const float4* w2r = reinterpret_cast<const float4*>(&sW2p[j * 12]);
        float4 wa = w2r[0], wb = w2r[1], wc = w2r[2];
        o[0] += h * wa.x; o[1]  += h * wa.y; o[2]  += h * wa.z; o[3]  += h * wa.w;
        o[4] += h * wb.x; o[5]  += h * wb.y; o[6]  += h * wb.z; o[7]  += h * wb.w;
        o[8] += h * wc.x; o[9]  += h * wc.y; o[10] += h * wc.z; o[11] += h * wc.w;
    }

    // new_pos = (pos + new_vel*DT) mod GRID (python floor-mod, b>0)
    float nx = fmodf(px + o[0] * DT, (float)GRIDSZ); if (nx < 0.0f) nx += (float)GRIDSZ;
    float ny = fmodf(py + o[1] * DT, (float)GRIDSZ); if (ny < 0.0f) ny += (float)GRIDSZ;

    out[0 * NAGENTS + i] = nx;
    out[1 * NAGENTS + i] = ny;
    out[2 * NAGENTS + i] = o[0];
    out[3 * NAGENTS + i] = o[1];

    // stage d_pheromone (channels 2..9) for the scatter pass
    float4 d0 = make_float4(o[2], o[3], o[4], o[5]);
    float4 d1 = make_float4(o[6], o[7], o[8], o[9]);
    float4* dp = reinterpret_cast<float4*>(&g_dpher[(size_t)i * NCH]);
    dp[0] = d0;
    dp[1] = d1;

    // deterministic duplicate resolution: max agent index wins (== last-wins
    // under sequential scatter). atomicMax is order-independent -> replayable.
    int pxi = (int)rintf(px);
    int pyi = (int)rintf(py);
    atomicMax(&g_winner[pxi * GRIDSZ + pyi], i + 1);
}

// ---------------------------------------------------------------------------
// Kernel 3: fused decay + scatter + winner reset, one streaming pass
// ---------------------------------------------------------------------------
__global__ void __launch_bounds__(256) latout_k(const float* __restrict__ lat,
                                               float* __restrict__ out) {
    int idx = blockIdx.x * blockDim.x + threadIdx.x;   // x*GRIDSZ + y
    if (idx >= GRIDSZ * GRIDSZ) return;
    int w = g_winner[idx];
    float up[NCH];
    if (w) {
        g_winner[idx] = 0;   // reset for next graph replay
        const float4* dp = reinterpret_cast<const float4*>(&g_dpher[(size_t)(w - 1) * NCH]);
        float4 a = dp[0], b = dp[1];
        up[0] = a.x; up[1] = a.y; up[2] = a.z; up[3] = a.w;
        up[4] = b.x; up[5] = b.y; up[6] = b.z; up[7] = b.w;
    }
    float* olat = out + 4 * NAGENTS;   // lattice section of output
    #pragma unroll
    for (int c = 0; c < NCH; c++) {
        float v = lat[(size_t)c * GRIDSZ * GRIDSZ + idx];
        if (w) v = fmaxf(v + DT * up[c], 0.0f);
        olat[(size_t)c * GRIDSZ * GRIDSZ + idx] = v * DECAY;
    }
}

// ---------------------------------------------------------------------------
extern "C" void kernel_launch(void* const* d_in, const int* in_sizes, int n_in,
                              void* d_out, int out_size) {
    const float* agent_pos = (const float*)d_in[0];   // (2, N)
    const float* agent_vel = (const float*)d_in[1];   // (2, N)
    const float* lattice   = (const float*)d_in[2];   // (8, 1024, 1024)
    const float* W1        = (const float*)d_in[3];   // (24, 64)
    const float* b1        = (const float*)d_in[4];   // (64,)
    const float* W2        = (const float*)d_in[5];   // (64, 10)
    const float* b2        = (const float*)d_in[6];   // (10,)
    float* out = (float*)d_out;

    const int cells = GRIDSZ * GRIDSZ;
    transpose_k<<<(cells + 255) / 256, 256>>>(lattice);
    agent_k<<<(NAGENTS + 255) / 256, 256>>>(agent_pos, agent_vel, W1, b1, W2, b2, out);
    latout_k<<<(cells + 255) / 256, 256>>>(lattice, out);
}